// round 13
// baseline (speedup 1.0000x reference)
#include <cuda_runtime.h>
#include <cuda_bf16.h>
#include <cstdint>

#define NA 100000
#define NB 100000
#define D 64
#define NTOT (NA + NA + NB)                 // deg/off layout: [aa->A | ba->A | ab->B]
#define ECAP 2000000
#define AS 72                               // smem row stride (bf16), conflict-free
#define CGRID 4096                          // 64x64 degree-pair grid (A); 1-D for B
#define TROWSA (CGRID + NA)
#define TROWSB (CGRID + NB)
#define SCAN_NBLK ((NTOT + 1023) / 1024)    // 293

// ======================= scratch (zero-initialized at module load) ===========
__device__ int      g_deg[NTOT];
__device__ unsigned g_state[SCAN_NBLK];
__device__ int      g_novf[2];
__device__ int      g_off[NTOT + 1];
__device__ int      g_cur[NTOT];
__device__ int      g_csr[ECAP];            // combo-id of src, grouped by dst
__device__ int      g_cidA[NA];
__device__ int      g_cidB[NB];
__device__ int2     g_ovfA[NA];
__device__ int      g_ovfB[NB];
__device__ float    g_vec[5 * D];           // cA, u_aa, u_ba, cB, u_ab
__device__ float    g_TzA[TROWSA * D];
__device__ float    g_Taa[TROWSA * D];
__device__ float    g_Tab[TROWSA * D];
__device__ float    g_TzB[TROWSB * D];
__device__ float    g_Tba[TROWSB * D];

// ======================= sparse machinery ====================================
__global__ void k_deg_all(const int* __restrict__ d_aa, int Eaa,
                          const int* __restrict__ d_ba, int Eba,
                          const int* __restrict__ d_ab, int Eab) {
    int i = blockIdx.x * blockDim.x + threadIdx.x;
    if (i < Eaa) {
        atomicAdd(&g_deg[d_aa[i]], 1);
    } else if (i < Eaa + Eba) {
        atomicAdd(&g_deg[NA + d_ba[i - Eaa]], 1);
    } else if (i < Eaa + Eba + Eab) {
        atomicAdd(&g_deg[2 * NA + d_ab[i - Eaa - Eba]], 1);
    }
}

// single-pass decoupled-lookback exclusive scan (warp-parallel lookback)
__global__ void __launch_bounds__(1024) k_scan_cid() {
    __shared__ int wsum[32];
    __shared__ int s_total, s_prefix;
    int b = blockIdx.x, t = threadIdx.x;
    int i = b * 1024 + t;
    int v = (i < NTOT) ? g_deg[i] : 0;
    int x = v;
#pragma unroll
    for (int o = 1; o < 32; o <<= 1) {
        int y = __shfl_up_sync(0xffffffffu, x, o);
        if ((t & 31) >= o) x += y;
    }
    if ((t & 31) == 31) wsum[t >> 5] = x;
    __syncthreads();
    if (t < 32) {
        int w = wsum[t];
        int xx = w;
#pragma unroll
        for (int o = 1; o < 32; o <<= 1) {
            int y = __shfl_up_sync(0xffffffffu, xx, o);
            if (t >= o) xx += y;
        }
        wsum[t] = xx - w;
        if (t == 31) {
            s_total = xx;
            unsigned st = ((b == 0 ? 2u : 1u) << 30) | (unsigned)xx;
            atomicExch(&g_state[b], st);
        }
    }
    __syncthreads();
    int excl = x - v + wsum[t >> 5];

    if (t < 32) {
        int pref = 0;
        if (b > 0) {
            int j = b - 1;
            while (true) {
                int idx = j - t;
                unsigned st;
                do {
                    st = (idx >= 0) ? atomicAdd(&g_state[idx], 0u) : (2u << 30);
                } while (__any_sync(0xffffffffu, (st >> 30) == 0));
                unsigned incmask = __ballot_sync(0xffffffffu, (st >> 30) >= 2);
                int firstInc = __ffs(incmask) - 1;
                int val = (int)(st & 0x3FFFFFFFu);
                int take = (firstInc >= 0) ? ((t <= firstInc) ? val : 0) : val;
#pragma unroll
                for (int o = 16; o; o >>= 1) take += __shfl_down_sync(0xffffffffu, take, o);
                take = __shfl_sync(0xffffffffu, take, 0);
                pref += take;
                if (firstInc >= 0) break;
                j -= 32;
            }
            if (t == 0) atomicExch(&g_state[b], (2u << 30) | (unsigned)(pref + s_total));
        }
        if (t == 0) s_prefix = pref;
    }
    __syncthreads();
    int off = s_prefix + excl;
    if (i < NTOT) { g_off[i] = off; g_cur[i] = off; }
    if (i == NTOT - 1) g_off[NTOT] = off + v;

    if (i < NA) {
        int d1 = v, d2 = g_deg[NA + i];
        int cid;
        if (d1 < 64 && d2 < 64) cid = d1 * 64 + d2;
        else { int o = atomicAdd(&g_novf[0], 1); g_ovfA[o] = make_int2(d1, d2); cid = CGRID + o; }
        g_cidA[i] = cid;
    } else if (i < NA + NB) {
        int d = g_deg[NA + i];
        int cid;
        if (d < CGRID) cid = d;
        else { int o = atomicAdd(&g_novf[1], 1); g_ovfB[o] = d; cid = CGRID + o; }
        g_cidB[i - NA] = cid;
    }
}

// counting-sort fill; stores the SRC COMBO-ID
__global__ void k_fill_all(const int* __restrict__ s_aa, const int* __restrict__ d_aa, int Eaa,
                           const int* __restrict__ s_ba, const int* __restrict__ d_ba, int Eba,
                           const int* __restrict__ s_ab, const int* __restrict__ d_ab, int Eab) {
    int i = blockIdx.x * blockDim.x + threadIdx.x;
    int cid, base, dstv;
    if (i < Eaa) { cid = __ldg(&g_cidA[s_aa[i]]); dstv = d_aa[i]; base = 0; }
    else if (i < Eaa + Eba) { int j = i - Eaa; cid = __ldg(&g_cidB[s_ba[j]]); dstv = d_ba[j]; base = NA; }
    else if (i < Eaa + Eba + Eab) { int j = i - Eaa - Eba; cid = __ldg(&g_cidA[s_ab[j]]); dstv = d_ab[j]; base = 2 * NA; }
    else return;
    int pos = atomicAdd(&g_cur[base + dstv], 1);
    g_csr[pos] = cid;
}

// zero scratch at END of run
__global__ void k_zero_end() {
    int i = blockIdx.x * blockDim.x + threadIdx.x;
    if (i < NTOT / 4) reinterpret_cast<int4*>(g_deg)[i] = make_int4(0, 0, 0, 0);
    if (i < SCAN_NBLK) g_state[i] = 0;
    if (i == 0) { g_novf[0] = 0; g_novf[1] = 0; }
}

// ======================= layer-0 closed form (1 block) ========================
__global__ void k_small(const float* __restrict__ embA, const float* __restrict__ embB,
                        const float* __restrict__ Waa, const float* __restrict__ baa,
                        const float* __restrict__ Wab, const float* __restrict__ bab,
                        const float* __restrict__ Wba, const float* __restrict__ bba,
                        const float* __restrict__ WnA, const float* __restrict__ bnA,
                        const float* __restrict__ WnB, const float* __restrict__ bnB) {
    __shared__ float sA[D], sB[D], vaa[D], vab[D], vba[D];
    int c = threadIdx.x;
    sA[c] = embA[c]; sB[c] = embB[c];
    __syncthreads();
    float a0 = baa[c], a1 = bab[c], a2 = bba[c];
    for (int k = 0; k < D; k++) {
        a0 += sA[k] * Waa[k * D + c];
        a1 += sA[k] * Wab[k * D + c];
        a2 += sB[k] * Wba[k * D + c];
    }
    vaa[c] = fmaxf(a0, 0.f); vab[c] = fmaxf(a1, 0.f); vba[c] = fmaxf(a2, 0.f);
    __syncthreads();
    float cA = bnA[c], uaa = 0.f, uba = 0.f, cB = bnB[c], uab = 0.f;
    for (int k = 0; k < D; k++) {
        cA  += sA[k]  * WnA[k * D + c];
        uaa += vaa[k] * WnA[(D + k) * D + c];
        uba += vba[k] * WnA[(2 * D + k) * D + c];
        cB  += sB[k]  * WnB[k * D + c];
        uab += vab[k] * WnB[(D + k) * D + c];
    }
    g_vec[c] = cA; g_vec[D + c] = uaa; g_vec[2 * D + c] = uba;
    g_vec[3 * D + c] = cB; g_vec[4 * D + c] = uab;
}

// ======================= MMA helpers =========================================
__device__ __forceinline__ void mma_bf16(float c[4], const uint32_t a[4],
                                         uint32_t b0, uint32_t b1) {
    asm volatile("mma.sync.aligned.m16n8k16.row.col.f32.bf16.bf16.f32 "
                 "{%0,%1,%2,%3}, {%4,%5,%6,%7}, {%8,%9}, {%0,%1,%2,%3};"
                 : "+f"(c[0]), "+f"(c[1]), "+f"(c[2]), "+f"(c[3])
                 : "r"(a[0]), "r"(a[1]), "r"(a[2]), "r"(a[3]), "r"(b0), "r"(b1));
}
__device__ __forceinline__ void pack_hl(float x, float y, uint32_t& hi, uint32_t& lo) {
    __nv_bfloat162 H, L;
    H.x = __float2bfloat16(x); H.y = __float2bfloat16(y);
    L.x = __float2bfloat16(x - __bfloat162float(H.x));
    L.y = __float2bfloat16(y - __bfloat162float(H.y));
    hi = *reinterpret_cast<uint32_t*>(&H);
    lo = *reinterpret_cast<uint32_t*>(&L);
}
__device__ __forceinline__ void gemm_tile(float acc[8][4],
                                          const uint32_t* Ahi, const uint32_t* Alo,
                                          const __nv_bfloat16* whi, int g, int t) {
    const __nv_bfloat16* wlo = whi + 64 * AS;
#pragma unroll
    for (int nt = 0; nt < 8; nt++) {
        const __nv_bfloat16* bh = whi + (nt * 8 + g) * AS + 2 * t;
        const __nv_bfloat16* bl = wlo + (nt * 8 + g) * AS + 2 * t;
#pragma unroll
        for (int kc = 0; kc < 4; kc++) {
            uint32_t bh0 = *reinterpret_cast<const uint32_t*>(bh + kc * 16);
            uint32_t bh1 = *reinterpret_cast<const uint32_t*>(bh + kc * 16 + 8);
            uint32_t bl0 = *reinterpret_cast<const uint32_t*>(bl + kc * 16);
            uint32_t bl1 = *reinterpret_cast<const uint32_t*>(bl + kc * 16 + 8);
            mma_bf16(acc[nt], &Ahi[kc * 4], bh0, bh1);
            mma_bf16(acc[nt], &Ahi[kc * 4], bl0, bl1);
            mma_bf16(acc[nt], &Alo[kc * 4], bh0, bh1);
        }
    }
}
__device__ __forceinline__ void c2a(float acc[8][4], const float* __restrict__ bias,
                                    uint32_t A2hi[16], uint32_t A2lo[16], int t) {
#pragma unroll
    for (int kc = 0; kc < 4; kc++) {
        int nt0 = 2 * kc, nt1 = nt0 + 1;
        float b00 = __ldg(bias + nt0 * 8 + 2 * t), b01 = __ldg(bias + nt0 * 8 + 2 * t + 1);
        float b10 = __ldg(bias + nt1 * 8 + 2 * t), b11 = __ldg(bias + nt1 * 8 + 2 * t + 1);
        float x0 = fmaxf(acc[nt0][0] + b00, 0.f), x1 = fmaxf(acc[nt0][1] + b01, 0.f);
        float x2 = fmaxf(acc[nt0][2] + b00, 0.f), x3 = fmaxf(acc[nt0][3] + b01, 0.f);
        float y0 = fmaxf(acc[nt1][0] + b10, 0.f), y1 = fmaxf(acc[nt1][1] + b11, 0.f);
        float y2 = fmaxf(acc[nt1][2] + b10, 0.f), y3 = fmaxf(acc[nt1][3] + b11, 0.f);
        pack_hl(x0, x1, A2hi[kc * 4 + 0], A2lo[kc * 4 + 0]);
        pack_hl(x2, x3, A2hi[kc * 4 + 1], A2lo[kc * 4 + 1]);
        pack_hl(y0, y1, A2hi[kc * 4 + 2], A2lo[kc * 4 + 2]);
        pack_hl(y2, y3, A2hi[kc * 4 + 3], A2lo[kc * 4 + 3]);
    }
}
__device__ __forceinline__ void store_tile(float acc[8][4], const float* __restrict__ bias,
                                           float* __restrict__ out, int row0, int row1,
                                           int R, int t) {
#pragma unroll
    for (int nt = 0; nt < 8; nt++) {
        int col = nt * 8 + 2 * t;
        float bx = bias ? __ldg(bias + col) : 0.f;
        float by = bias ? __ldg(bias + col + 1) : 0.f;
        float2 v0 = make_float2(acc[nt][0] + bx, acc[nt][1] + by);
        float2 v1 = make_float2(acc[nt][2] + bx, acc[nt][3] + by);
        if (row0 < R) *reinterpret_cast<float2*>(out + (size_t)row0 * 64 + col) = v0;
        if (row1 < R) *reinterpret_cast<float2*>(out + (size_t)row1 * 64 + col) = v1;
    }
}
// stage one weight matrix [64,64] (transposed to [n][k]) as hi/lo into smem slot
__device__ __forceinline__ void stage_one(__nv_bfloat16* slot, const float* __restrict__ w,
                                          int tid) {
    for (int i = tid; i < 4096; i += 256) {
        int k = i >> 6, n = i & 63;
        float x = w[i];
        __nv_bfloat16 hi = __float2bfloat16(x);
        slot[n * AS + k] = hi;
        slot[64 * AS + n * AS + k] = __float2bfloat16(x - __bfloat162float(hi));
    }
}

// ======================= per-table combo GEMM kernels =========================
// blockIdx.y = mode. Static smem: 2 slots x (hi+lo) = 36864 B.
#define SLOT (2 * 64 * AS)

__global__ void __launch_bounds__(256) k_gemmA_v2(
        const float* __restrict__ Waa1, const float* __restrict__ baa1,
        const float* __restrict__ Wab1, const float* __restrict__ bab1,
        const float* __restrict__ WnA1, const float* __restrict__ bnA1,
        const float* __restrict__ WnB1blk1, int is_ovf) {
    int nrows = is_ovf ? g_novf[0] : CGRID;
    if ((int)blockIdx.x * 128 >= nrows) return;
    int row_off = is_ovf ? CGRID : 0;
    int limit = row_off + nrows;
    int mode = blockIdx.y;

    const float *W1 = nullptr, *b1 = nullptr, *W2;
    const float* bout = nullptr;
    float* OUT;
    if (mode == 0)      { W2 = WnA1;        bout = bnA1; OUT = g_TzA; }
    else if (mode == 1) { W1 = Waa1; b1 = baa1; W2 = WnA1 + 4096; OUT = g_Taa; }
    else                { W1 = Wab1; b1 = bab1; W2 = WnB1blk1;    OUT = g_Tab; }

    __shared__ __nv_bfloat16 sm[2 * SLOT];
    int tid = threadIdx.x;
    stage_one(sm, W2, tid);                  // slot 0 = W2
    if (W1) stage_one(sm + SLOT, W1, tid);   // slot 1 = W1
    __syncthreads();

    int lane = tid & 31, wid = tid >> 5;
    int g = lane >> 2, t = lane & 3;
    int row0 = row_off + blockIdx.x * 128 + wid * 16 + g, row1 = row0 + 8;
    int r0 = min(row0, limit - 1), r1 = min(row1, limit - 1);
    float d10, d20, d11, d21;
    if (r0 < CGRID) { d10 = (float)(r0 >> 6); d20 = (float)(r0 & 63); }
    else { int2 dd = g_ovfA[r0 - CGRID]; d10 = (float)dd.x; d20 = (float)dd.y; }
    if (r1 < CGRID) { d11 = (float)(r1 >> 6); d21 = (float)(r1 & 63); }
    else { int2 dd = g_ovfA[r1 - CGRID]; d11 = (float)dd.x; d21 = (float)dd.y; }

    // h fragments from g_vec (precomputed by k_small)
    uint32_t Ahi[16], Alo[16];
#pragma unroll
    for (int kc = 0; kc < 4; kc++) {
        int c0 = kc * 16 + 2 * t;
#pragma unroll
        for (int half = 0; half < 2; half++) {
            int c = c0 + half * 8;
            float p0 = __ldg(g_vec + c),     u0 = __ldg(g_vec + 64 + c),     w0 = __ldg(g_vec + 128 + c);
            float p1 = __ldg(g_vec + c + 1), u1 = __ldg(g_vec + 64 + c + 1), w1 = __ldg(g_vec + 128 + c + 1);
            float h00 = fmaxf(p0 + d10 * u0 + d20 * w0, 0.f);
            float h01 = fmaxf(p1 + d10 * u1 + d20 * w1, 0.f);
            float h10 = fmaxf(p0 + d11 * u0 + d21 * w0, 0.f);
            float h11 = fmaxf(p1 + d11 * u1 + d21 * w1, 0.f);
            pack_hl(h00, h01, Ahi[kc * 4 + half * 2 + 0], Alo[kc * 4 + half * 2 + 0]);
            pack_hl(h10, h11, Ahi[kc * 4 + half * 2 + 1], Alo[kc * 4 + half * 2 + 1]);
        }
    }

    float acc[8][4];
#pragma unroll
    for (int nt = 0; nt < 8; nt++) { acc[nt][0]=0.f; acc[nt][1]=0.f; acc[nt][2]=0.f; acc[nt][3]=0.f; }

    if (W1) {
        gemm_tile(acc, Ahi, Alo, sm + SLOT, g, t);       // stage 1: h @ W1
        uint32_t A2hi[16], A2lo[16];
        c2a(acc, b1, A2hi, A2lo, t);                     // +bias, relu, repack
        float acc2[8][4];
#pragma unroll
        for (int nt = 0; nt < 8; nt++) { acc2[nt][0]=0.f; acc2[nt][1]=0.f; acc2[nt][2]=0.f; acc2[nt][3]=0.f; }
        gemm_tile(acc2, A2hi, A2lo, sm, g, t);           // stage 2: m @ W2
        store_tile(acc2, nullptr, OUT, row0, row1, limit, t);
    } else {
        gemm_tile(acc, Ahi, Alo, sm, g, t);              // single: h @ W2
        store_tile(acc, bout, OUT, row0, row1, limit, t);
    }
}

__global__ void __launch_bounds__(256) k_gemmB_v2(
        const float* __restrict__ Wba1, const float* __restrict__ bba1,
        const float* __restrict__ WnB1, const float* __restrict__ bnB1,
        const float* __restrict__ WnA1blk2, int is_ovf) {
    int nrows = is_ovf ? g_novf[1] : CGRID;
    if ((int)blockIdx.x * 128 >= nrows) return;
    int row_off = is_ovf ? CGRID : 0;
    int limit = row_off + nrows;
    int mode = blockIdx.y;

    const float *W1 = nullptr, *b1 = nullptr, *W2;
    const float* bout = nullptr;
    float* OUT;
    if (mode == 0) { W2 = WnB1; bout = bnB1; OUT = g_TzB; }
    else           { W1 = Wba1; b1 = bba1; W2 = WnA1blk2; OUT = g_Tba; }

    __shared__ __nv_bfloat16 sm[2 * SLOT];
    int tid = threadIdx.x;
    stage_one(sm, W2, tid);
    if (W1) stage_one(sm + SLOT, W1, tid);
    __syncthreads();

    int lane = tid & 31, wid = tid >> 5;
    int g = lane >> 2, t = lane & 3;
    int row0 = row_off + blockIdx.x * 128 + wid * 16 + g, row1 = row0 + 8;
    int r0 = min(row0, limit - 1), r1 = min(row1, limit - 1);
    float d0 = (r0 < CGRID) ? (float)r0 : (float)g_ovfB[r0 - CGRID];
    float d1 = (r1 < CGRID) ? (float)r1 : (float)g_ovfB[r1 - CGRID];

    uint32_t Ahi[16], Alo[16];
#pragma unroll
    for (int kc = 0; kc < 4; kc++) {
        int c0 = kc * 16 + 2 * t;
#pragma unroll
        for (int half = 0; half < 2; half++) {
            int c = c0 + half * 8;
            float p0 = __ldg(g_vec + 192 + c),     u0 = __ldg(g_vec + 256 + c);
            float p1 = __ldg(g_vec + 192 + c + 1), u1 = __ldg(g_vec + 256 + c + 1);
            float h00 = fmaxf(p0 + d0 * u0, 0.f);
            float h01 = fmaxf(p1 + d0 * u1, 0.f);
            float h10 = fmaxf(p0 + d1 * u0, 0.f);
            float h11 = fmaxf(p1 + d1 * u1, 0.f);
            pack_hl(h00, h01, Ahi[kc * 4 + half * 2 + 0], Alo[kc * 4 + half * 2 + 0]);
            pack_hl(h10, h11, Ahi[kc * 4 + half * 2 + 1], Alo[kc * 4 + half * 2 + 1]);
        }
    }

    float acc[8][4];
#pragma unroll
    for (int nt = 0; nt < 8; nt++) { acc[nt][0]=0.f; acc[nt][1]=0.f; acc[nt][2]=0.f; acc[nt][3]=0.f; }

    if (W1) {
        gemm_tile(acc, Ahi, Alo, sm + SLOT, g, t);
        uint32_t A2hi[16], A2lo[16];
        c2a(acc, b1, A2hi, A2lo, t);
        float acc2[8][4];
#pragma unroll
        for (int nt = 0; nt < 8; nt++) { acc2[nt][0]=0.f; acc2[nt][1]=0.f; acc2[nt][2]=0.f; acc2[nt][3]=0.f; }
        gemm_tile(acc2, A2hi, A2lo, sm, g, t);
        store_tile(acc2, nullptr, OUT, row0, row1, limit, t);
    } else {
        gemm_tile(acc, Ahi, Alo, sm, g, t);
        store_tile(acc, bout, OUT, row0, row1, limit, t);
    }
}

// ======================= fused gather =========================================
__device__ __forceinline__ void seg_sum(float2& s, int b, int e,
                                        const float* __restrict__ T, int lane) {
    int cnt = e - b;
    for (int base = 0; base < cnt; base += 32) {
        int rem = cnt - base;
        int m = rem < 32 ? rem : 32;
        int idx = (lane < m) ? __ldg(&g_csr[b + base + lane]) : 0;
        int k = 0;
        for (; k + 1 < m; k += 2) {
            int c0 = __shfl_sync(0xffffffffu, idx, k);
            int c1 = __shfl_sync(0xffffffffu, idx, k + 1);
            float2 p = *reinterpret_cast<const float2*>(T + (size_t)c0 * 64 + lane * 2);
            float2 q = *reinterpret_cast<const float2*>(T + (size_t)c1 * 64 + lane * 2);
            s.x += p.x + q.x; s.y += p.y + q.y;
        }
        if (k < m) {
            int c0 = __shfl_sync(0xffffffffu, idx, k);
            float2 p = *reinterpret_cast<const float2*>(T + (size_t)c0 * 64 + lane * 2);
            s.x += p.x; s.y += p.y;
        }
    }
}

__global__ void __launch_bounds__(256) k_gather(float* __restrict__ out) {
    int row = blockIdx.x * 8 + (threadIdx.x >> 5);
    if (row >= NA + NB) return;
    int lane = threadIdx.x & 31;
    float2 s;
    if (row < NA) {
        int cself = __ldg(&g_cidA[row]);
        s = *reinterpret_cast<const float2*>(g_TzA + (size_t)cself * 64 + lane * 2);
        seg_sum(s, g_off[row],      g_off[row + 1],      g_Taa, lane);
        seg_sum(s, g_off[NA + row], g_off[NA + row + 1], g_Tba, lane);
    } else {
        int rb = row - NA;
        int cself = __ldg(&g_cidB[rb]);
        s = *reinterpret_cast<const float2*>(g_TzB + (size_t)cself * 64 + lane * 2);
        seg_sum(s, g_off[2 * NA + rb], g_off[2 * NA + rb + 1], g_Tab, lane);
    }
    s.x = fmaxf(s.x, 0.f); s.y = fmaxf(s.y, 0.f);
    *reinterpret_cast<float2*>(out + (size_t)row * 64 + lane * 2) = s;
}

// ==============================================================================
struct Aux {
    cudaStream_t s2;
    cudaEvent_t evF, evS, evJ;
    Aux() {
        cudaStreamCreateWithFlags(&s2, cudaStreamNonBlocking);
        cudaEventCreateWithFlags(&evF, cudaEventDisableTiming);
        cudaEventCreateWithFlags(&evS, cudaEventDisableTiming);
        cudaEventCreateWithFlags(&evJ, cudaEventDisableTiming);
    }
};

extern "C" void kernel_launch(void* const* d_in, const int* in_sizes, int n_in,
                              void* d_out, int out_size) {
    static Aux aux;

    const int*   src_aa = (const int*)d_in[0];
    const int*   dst_aa = (const int*)d_in[1];
    const int*   src_ab = (const int*)d_in[2];
    const int*   dst_ab = (const int*)d_in[3];
    const int*   src_ba = (const int*)d_in[4];
    const int*   dst_ba = (const int*)d_in[5];
    const float* embA   = (const float*)d_in[6];
    const float* embB   = (const float*)d_in[7];
    const float* Waa    = (const float*)d_in[8];
    const float* baa    = (const float*)d_in[9];
    const float* Wab    = (const float*)d_in[10];
    const float* bab    = (const float*)d_in[11];
    const float* Wba    = (const float*)d_in[12];
    const float* bba    = (const float*)d_in[13];
    const float* WnA    = (const float*)d_in[14];
    const float* bnA    = (const float*)d_in[15];
    const float* WnB    = (const float*)d_in[16];
    const float* bnB    = (const float*)d_in[17];
    const int Eaa = in_sizes[0];
    const int Eab = in_sizes[2];
    const int Eba = in_sizes[4];
    const int Etot = Eaa + Eba + Eab;
    float* out = (float*)d_out;

    const float* Waa1 = Waa + 4096;
    const float* Wab1 = Wab + 4096;
    const float* Wba1 = Wba + 4096;
    const float* baa1 = baa + 64;
    const float* bab1 = bab + 64;
    const float* bba1 = bba + 64;
    const float* WnA1 = WnA + 192 * 64;
    const float* WnB1 = WnB + 128 * 64;
    const float* bnA1 = bnA + 64;
    const float* bnB1 = bnB + 64;

    // fork: closed-form vec + combo-grid tables (weights-only deps) -> s2
    cudaEventRecord(aux.evF, 0);
    cudaStreamWaitEvent(aux.s2, aux.evF, 0);
    k_small<<<1, 64, 0, aux.s2>>>(embA, embB, Waa, baa, Wab, bab, Wba, bba,
                                  WnA, bnA, WnB, bnB);
    k_gemmA_v2<<<dim3(CGRID / 128, 3), 256, 0, aux.s2>>>(
        Waa1, baa1, Wab1, bab1, WnA1, bnA1, WnB1 + 4096, 0);
    k_gemmB_v2<<<dim3(CGRID / 128, 2), 256, 0, aux.s2>>>(
        Wba1, bba1, WnB1, bnB1, WnA1 + 2 * 4096, 0);

    // main chain: deg -> single-pass scan+cid
    k_deg_all<<<(Etot + 255) / 256, 256>>>(dst_aa, Eaa, dst_ba, Eba, dst_ab, Eab);
    k_scan_cid<<<SCAN_NBLK, 1024>>>();

    // overflow rows on s2 (depend on scan), concurrent with fill
    cudaEventRecord(aux.evS, 0);
    cudaStreamWaitEvent(aux.s2, aux.evS, 0);
    k_gemmA_v2<<<dim3((NA + 127) / 128, 3), 256, 0, aux.s2>>>(
        Waa1, baa1, Wab1, bab1, WnA1, bnA1, WnB1 + 4096, 1);
    k_gemmB_v2<<<dim3((NB + 127) / 128, 2), 256, 0, aux.s2>>>(
        Wba1, bba1, WnB1, bnB1, WnA1 + 2 * 4096, 1);
    cudaEventRecord(aux.evJ, aux.s2);

    k_fill_all<<<(Etot + 255) / 256, 256>>>(src_aa, dst_aa, Eaa,
                                            src_ba, dst_ba, Eba,
                                            src_ab, dst_ab, Eab);

    // join, gather, reset scratch (main stream)
    cudaStreamWaitEvent(0, aux.evJ, 0);
    k_gather<<<(NA + NB + 7) / 8, 256>>>(out);
    k_zero_end<<<(NTOT / 4 + 255) / 256, 256>>>();
}

// round 14
// speedup vs baseline: 1.2738x; 1.2738x over previous
#include <cuda_runtime.h>
#include <cuda_bf16.h>
#include <cstdint>

#define NA 100000
#define NB 100000
#define D 64
#define NTOT (NA + NA + NB)                 // deg/off layout: [aa->A | ba->A | ab->B]
#define ECAP 2000000
#define AS 72                               // smem row stride (bf16), conflict-free
#define CGRID 4096                          // 64x64 degree-pair grid (A); 1-D for B
#define TROWSA (CGRID + NA)
#define TROWSB (CGRID + NB)
#define SCAN_NBLK ((NTOT + 1023) / 1024)    // 293
#define SLOT (2 * 64 * AS)

// ======================= scratch (zero-initialized at module load) ===========
__device__ int      g_deg[NTOT];            // zeroed inside k_gather each run
__device__ unsigned g_state[SCAN_NBLK];     // zeroed inside k_gather each run
__device__ int      g_novf[2];              // zeroed inside k_gather each run
__device__ int      g_off[NTOT + 1];
__device__ int      g_cur[NTOT];
__device__ int      g_csr[ECAP];            // combo-id of src, grouped by dst
__device__ int      g_cidA[NA];
__device__ int      g_cidB[NB];
__device__ int2     g_ovfA[NA];
__device__ int      g_ovfB[NB];
__device__ float    g_TzA[TROWSA * D];
__device__ float    g_Taa[TROWSA * D];
__device__ float    g_Tab[TROWSA * D];
__device__ float    g_TzB[TROWSB * D];
__device__ float    g_Tba[TROWSB * D];

// ======================= sparse machinery ====================================
__global__ void k_deg_all(const int* __restrict__ d_aa, int Eaa,
                          const int* __restrict__ d_ba, int Eba,
                          const int* __restrict__ d_ab, int Eab) {
    int i = blockIdx.x * blockDim.x + threadIdx.x;
    if (i < Eaa) {
        atomicAdd(&g_deg[d_aa[i]], 1);
    } else if (i < Eaa + Eba) {
        atomicAdd(&g_deg[NA + d_ba[i - Eaa]], 1);
    } else if (i < Eaa + Eba + Eab) {
        atomicAdd(&g_deg[2 * NA + d_ab[i - Eaa - Eba]], 1);
    }
}

// single-pass decoupled-lookback exclusive scan (warp-parallel lookback)
__global__ void __launch_bounds__(1024) k_scan_cid() {
    __shared__ int wsum[32];
    __shared__ int s_total, s_prefix;
    int b = blockIdx.x, t = threadIdx.x;
    int i = b * 1024 + t;
    int v = (i < NTOT) ? g_deg[i] : 0;
    int x = v;
#pragma unroll
    for (int o = 1; o < 32; o <<= 1) {
        int y = __shfl_up_sync(0xffffffffu, x, o);
        if ((t & 31) >= o) x += y;
    }
    if ((t & 31) == 31) wsum[t >> 5] = x;
    __syncthreads();
    if (t < 32) {
        int w = wsum[t];
        int xx = w;
#pragma unroll
        for (int o = 1; o < 32; o <<= 1) {
            int y = __shfl_up_sync(0xffffffffu, xx, o);
            if (t >= o) xx += y;
        }
        wsum[t] = xx - w;
        if (t == 31) {
            s_total = xx;
            unsigned st = ((b == 0 ? 2u : 1u) << 30) | (unsigned)xx;
            atomicExch(&g_state[b], st);
        }
    }
    __syncthreads();
    int excl = x - v + wsum[t >> 5];

    if (t < 32) {
        int pref = 0;
        if (b > 0) {
            int j = b - 1;
            while (true) {
                int idx = j - t;
                unsigned st;
                do {
                    st = (idx >= 0) ? atomicAdd(&g_state[idx], 0u) : (2u << 30);
                } while (__any_sync(0xffffffffu, (st >> 30) == 0));
                unsigned incmask = __ballot_sync(0xffffffffu, (st >> 30) >= 2);
                int firstInc = __ffs(incmask) - 1;
                int val = (int)(st & 0x3FFFFFFFu);
                int take = (firstInc >= 0) ? ((t <= firstInc) ? val : 0) : val;
#pragma unroll
                for (int o = 16; o; o >>= 1) take += __shfl_down_sync(0xffffffffu, take, o);
                take = __shfl_sync(0xffffffffu, take, 0);
                pref += take;
                if (firstInc >= 0) break;
                j -= 32;
            }
            if (t == 0) atomicExch(&g_state[b], (2u << 30) | (unsigned)(pref + s_total));
        }
        if (t == 0) s_prefix = pref;
    }
    __syncthreads();
    int off = s_prefix + excl;
    if (i < NTOT) { g_off[i] = off; g_cur[i] = off; }
    if (i == NTOT - 1) g_off[NTOT] = off + v;

    if (i < NA) {
        int d1 = v, d2 = g_deg[NA + i];
        int cid;
        if (d1 < 64 && d2 < 64) cid = d1 * 64 + d2;
        else { int o = atomicAdd(&g_novf[0], 1); g_ovfA[o] = make_int2(d1, d2); cid = CGRID + o; }
        g_cidA[i] = cid;
    } else if (i < NA + NB) {
        int d = g_deg[NA + i];
        int cid;
        if (d < CGRID) cid = d;
        else { int o = atomicAdd(&g_novf[1], 1); g_ovfB[o] = d; cid = CGRID + o; }
        g_cidB[i - NA] = cid;
    }
}

// counting-sort fill; stores the SRC COMBO-ID
__global__ void k_fill_all(const int* __restrict__ s_aa, const int* __restrict__ d_aa, int Eaa,
                           const int* __restrict__ s_ba, const int* __restrict__ d_ba, int Eba,
                           const int* __restrict__ s_ab, const int* __restrict__ d_ab, int Eab) {
    int i = blockIdx.x * blockDim.x + threadIdx.x;
    int cid, base, dstv;
    if (i < Eaa) { cid = __ldg(&g_cidA[s_aa[i]]); dstv = d_aa[i]; base = 0; }
    else if (i < Eaa + Eba) { int j = i - Eaa; cid = __ldg(&g_cidB[s_ba[j]]); dstv = d_ba[j]; base = NA; }
    else if (i < Eaa + Eba + Eab) { int j = i - Eaa - Eba; cid = __ldg(&g_cidA[s_ab[j]]); dstv = d_ab[j]; base = 2 * NA; }
    else return;
    int pos = atomicAdd(&g_cur[base + dstv], 1);
    g_csr[pos] = cid;
}

// ======================= MMA helpers =========================================
__device__ __forceinline__ void mma_bf16(float c[4], const uint32_t a[4],
                                         uint32_t b0, uint32_t b1) {
    asm volatile("mma.sync.aligned.m16n8k16.row.col.f32.bf16.bf16.f32 "
                 "{%0,%1,%2,%3}, {%4,%5,%6,%7}, {%8,%9}, {%0,%1,%2,%3};"
                 : "+f"(c[0]), "+f"(c[1]), "+f"(c[2]), "+f"(c[3])
                 : "r"(a[0]), "r"(a[1]), "r"(a[2]), "r"(a[3]), "r"(b0), "r"(b1));
}
__device__ __forceinline__ void pack_hl(float x, float y, uint32_t& hi, uint32_t& lo) {
    __nv_bfloat162 H, L;
    H.x = __float2bfloat16(x); H.y = __float2bfloat16(y);
    L.x = __float2bfloat16(x - __bfloat162float(H.x));
    L.y = __float2bfloat16(y - __bfloat162float(H.y));
    hi = *reinterpret_cast<uint32_t*>(&H);
    lo = *reinterpret_cast<uint32_t*>(&L);
}
__device__ __forceinline__ void gemm_tile(float acc[8][4],
                                          const uint32_t* Ahi, const uint32_t* Alo,
                                          const __nv_bfloat16* whi, int g, int t) {
    const __nv_bfloat16* wlo = whi + 64 * AS;
#pragma unroll
    for (int nt = 0; nt < 8; nt++) {
        const __nv_bfloat16* bh = whi + (nt * 8 + g) * AS + 2 * t;
        const __nv_bfloat16* bl = wlo + (nt * 8 + g) * AS + 2 * t;
#pragma unroll
        for (int kc = 0; kc < 4; kc++) {
            uint32_t bh0 = *reinterpret_cast<const uint32_t*>(bh + kc * 16);
            uint32_t bh1 = *reinterpret_cast<const uint32_t*>(bh + kc * 16 + 8);
            uint32_t bl0 = *reinterpret_cast<const uint32_t*>(bl + kc * 16);
            uint32_t bl1 = *reinterpret_cast<const uint32_t*>(bl + kc * 16 + 8);
            mma_bf16(acc[nt], &Ahi[kc * 4], bh0, bh1);
            mma_bf16(acc[nt], &Ahi[kc * 4], bl0, bl1);
            mma_bf16(acc[nt], &Alo[kc * 4], bh0, bh1);
        }
    }
}
__device__ __forceinline__ void c2a(float acc[8][4], const float* __restrict__ bias,
                                    uint32_t A2hi[16], uint32_t A2lo[16], int t) {
#pragma unroll
    for (int kc = 0; kc < 4; kc++) {
        int nt0 = 2 * kc, nt1 = nt0 + 1;
        float b00 = __ldg(bias + nt0 * 8 + 2 * t), b01 = __ldg(bias + nt0 * 8 + 2 * t + 1);
        float b10 = __ldg(bias + nt1 * 8 + 2 * t), b11 = __ldg(bias + nt1 * 8 + 2 * t + 1);
        float x0 = fmaxf(acc[nt0][0] + b00, 0.f), x1 = fmaxf(acc[nt0][1] + b01, 0.f);
        float x2 = fmaxf(acc[nt0][2] + b00, 0.f), x3 = fmaxf(acc[nt0][3] + b01, 0.f);
        float y0 = fmaxf(acc[nt1][0] + b10, 0.f), y1 = fmaxf(acc[nt1][1] + b11, 0.f);
        float y2 = fmaxf(acc[nt1][2] + b10, 0.f), y3 = fmaxf(acc[nt1][3] + b11, 0.f);
        pack_hl(x0, x1, A2hi[kc * 4 + 0], A2lo[kc * 4 + 0]);
        pack_hl(x2, x3, A2hi[kc * 4 + 1], A2lo[kc * 4 + 1]);
        pack_hl(y0, y1, A2hi[kc * 4 + 2], A2lo[kc * 4 + 2]);
        pack_hl(y2, y3, A2hi[kc * 4 + 3], A2lo[kc * 4 + 3]);
    }
}
__device__ __forceinline__ void store_tile(float acc[8][4], const float* __restrict__ bias,
                                           float* __restrict__ out, int row0, int row1,
                                           int R, int t) {
#pragma unroll
    for (int nt = 0; nt < 8; nt++) {
        int col = nt * 8 + 2 * t;
        float bx = bias ? __ldg(bias + col) : 0.f;
        float by = bias ? __ldg(bias + col + 1) : 0.f;
        float2 v0 = make_float2(acc[nt][0] + bx, acc[nt][1] + by);
        float2 v1 = make_float2(acc[nt][2] + bx, acc[nt][3] + by);
        if (row0 < R) *reinterpret_cast<float2*>(out + (size_t)row0 * 64 + col) = v0;
        if (row1 < R) *reinterpret_cast<float2*>(out + (size_t)row1 * 64 + col) = v1;
    }
}
__device__ __forceinline__ void stage_one(__nv_bfloat16* slot, const float* __restrict__ w,
                                          int tid) {
    for (int i = tid; i < 4096; i += 256) {
        int k = i >> 6, n = i & 63;
        float x = __ldg(w + i);
        __nv_bfloat16 hi = __float2bfloat16(x);
        slot[n * AS + k] = hi;
        slot[64 * AS + n * AS + k] = __float2bfloat16(x - __bfloat162float(hi));
    }
}

// ======================= unified combo-table kernel ===========================
// blockIdx.y = mode: 0 TzA, 1 Taa, 2 Tab (A tables); 3 TzB, 4 Tba (B tables).
// is_ovf=0: combo grid rows [0,CGRID), grid (32,5).
// is_ovf=1: overflow rows, grid-strided, grid (8,5); exits when novf==0.
__global__ void __launch_bounds__(256) k_tables(
        const float* __restrict__ embA, const float* __restrict__ embB,
        const float* __restrict__ Waa, const float* __restrict__ baa,
        const float* __restrict__ Wab, const float* __restrict__ bab,
        const float* __restrict__ Wba, const float* __restrict__ bba,
        const float* __restrict__ WnA, const float* __restrict__ bnA,
        const float* __restrict__ WnB, const float* __restrict__ bnB,
        int is_ovf) {
    int mode = blockIdx.y;
    bool isA = (mode < 3);
    int novf = is_ovf ? (isA ? g_novf[0] : g_novf[1]) : 0;
    if (is_ovf && novf == 0) return;

    const float* Waa1 = Waa + 4096; const float* baa1 = baa + 64;
    const float* Wab1 = Wab + 4096; const float* bab1 = bab + 64;
    const float* Wba1 = Wba + 4096; const float* bba1 = bba + 64;
    const float* WnA1 = WnA + 192 * 64; const float* bnA1 = bnA + 64;
    const float* WnB1 = WnB + 128 * 64; const float* bnB1 = bnB + 64;

    const float *W1 = nullptr, *b1 = nullptr, *W2;
    const float* bout = nullptr;
    float* OUT;
    switch (mode) {
        case 0:  W2 = WnA1;        bout = bnA1;               OUT = g_TzA; break;
        case 1:  W1 = Waa1; b1 = baa1; W2 = WnA1 + 4096;      OUT = g_Taa; break;
        case 2:  W1 = Wab1; b1 = bab1; W2 = WnB1 + 4096;      OUT = g_Tab; break;
        case 3:  W2 = WnB1;        bout = bnB1;               OUT = g_TzB; break;
        default: W1 = Wba1; b1 = bba1; W2 = WnA1 + 8192;      OUT = g_Tba; break;
    }

    __shared__ __nv_bfloat16 sm[2 * SLOT];          // 36864 B
    __shared__ float sA[64], sB[64], v1[64], v2[64], v3[64], sv[5 * 64];
    int tid = threadIdx.x;
    stage_one(sm, W2, tid);
    if (W1) stage_one(sm + SLOT, W1, tid);
    if (tid < 64) { sA[tid] = __ldg(embA + tid); sB[tid] = __ldg(embB + tid); }
    __syncthreads();
    if (tid < 64) {
        int c = tid;
        float a0 = __ldg(baa + c), a1 = __ldg(bab + c), a2 = __ldg(bba + c);
        for (int k = 0; k < 64; k++) {
            a0 += sA[k] * __ldg(Waa + k * 64 + c);
            a1 += sA[k] * __ldg(Wab + k * 64 + c);
            a2 += sB[k] * __ldg(Wba + k * 64 + c);
        }
        v1[c] = fmaxf(a0, 0.f); v2[c] = fmaxf(a1, 0.f); v3[c] = fmaxf(a2, 0.f);
    }
    __syncthreads();
    if (tid < 64) {
        int c = tid;
        float cA = __ldg(bnA + c), uaa = 0.f, uba = 0.f;
        float cB = __ldg(bnB + c), uab = 0.f;
        for (int k = 0; k < 64; k++) {
            cA  += sA[k] * __ldg(WnA + k * 64 + c);
            uaa += v1[k] * __ldg(WnA + (64 + k) * 64 + c);
            uba += v3[k] * __ldg(WnA + (128 + k) * 64 + c);
            cB  += sB[k] * __ldg(WnB + k * 64 + c);
            uab += v2[k] * __ldg(WnB + (64 + k) * 64 + c);
        }
        sv[c] = cA; sv[64 + c] = uaa; sv[128 + c] = uba;
        sv[192 + c] = cB; sv[256 + c] = uab;
    }
    __syncthreads();

    int lane = tid & 31, wid = tid >> 5;
    int g = lane >> 2, t = lane & 3;
    const float* bse = isA ? sv : sv + 192;
    int row_off = is_ovf ? CGRID : 0;
    int nrows   = is_ovf ? novf : CGRID;
    int limit   = row_off + nrows;
    int tiles   = (nrows + 127) / 128;

    for (int tile = blockIdx.x; tile < tiles; tile += gridDim.x) {
        int row0 = row_off + tile * 128 + wid * 16 + g, row1 = row0 + 8;
        int r0 = min(row0, limit - 1), r1 = min(row1, limit - 1);
        float d10, d20, d11, d21;
        if (isA) {
            if (r0 < CGRID) { d10 = (float)(r0 >> 6); d20 = (float)(r0 & 63); }
            else { int2 dd = g_ovfA[r0 - CGRID]; d10 = (float)dd.x; d20 = (float)dd.y; }
            if (r1 < CGRID) { d11 = (float)(r1 >> 6); d21 = (float)(r1 & 63); }
            else { int2 dd = g_ovfA[r1 - CGRID]; d11 = (float)dd.x; d21 = (float)dd.y; }
        } else {
            d10 = (r0 < CGRID) ? (float)r0 : (float)g_ovfB[r0 - CGRID]; d20 = 0.f;
            d11 = (r1 < CGRID) ? (float)r1 : (float)g_ovfB[r1 - CGRID]; d21 = 0.f;
        }

        uint32_t Ahi[16], Alo[16];
#pragma unroll
        for (int kc = 0; kc < 4; kc++) {
            int c0 = kc * 16 + 2 * t;
#pragma unroll
            for (int half = 0; half < 2; half++) {
                int c = c0 + half * 8;
                float p0 = bse[c],     u0 = bse[64 + c];
                float p1 = bse[c + 1], u1 = bse[64 + c + 1];
                float w0 = isA ? bse[128 + c]     : 0.f;
                float w1 = isA ? bse[128 + c + 1] : 0.f;
                float h00 = fmaxf(p0 + d10 * u0 + d20 * w0, 0.f);
                float h01 = fmaxf(p1 + d10 * u1 + d20 * w1, 0.f);
                float h10 = fmaxf(p0 + d11 * u0 + d21 * w0, 0.f);
                float h11 = fmaxf(p1 + d11 * u1 + d21 * w1, 0.f);
                pack_hl(h00, h01, Ahi[kc * 4 + half * 2 + 0], Alo[kc * 4 + half * 2 + 0]);
                pack_hl(h10, h11, Ahi[kc * 4 + half * 2 + 1], Alo[kc * 4 + half * 2 + 1]);
            }
        }

        float acc[8][4];
#pragma unroll
        for (int nt = 0; nt < 8; nt++) { acc[nt][0]=0.f; acc[nt][1]=0.f; acc[nt][2]=0.f; acc[nt][3]=0.f; }

        if (W1) {
            gemm_tile(acc, Ahi, Alo, sm + SLOT, g, t);       // stage 1: h @ W1
            uint32_t A2hi[16], A2lo[16];
            c2a(acc, b1, A2hi, A2lo, t);
            float acc2[8][4];
#pragma unroll
            for (int nt = 0; nt < 8; nt++) { acc2[nt][0]=0.f; acc2[nt][1]=0.f; acc2[nt][2]=0.f; acc2[nt][3]=0.f; }
            gemm_tile(acc2, A2hi, A2lo, sm, g, t);           // stage 2: m @ W2
            store_tile(acc2, nullptr, OUT, row0, row1, limit, t);
        } else {
            gemm_tile(acc, Ahi, Alo, sm, g, t);
            store_tile(acc, bout, OUT, row0, row1, limit, t);
        }
    }
}

// ======================= fused gather (+scratch zeroing) ======================
__device__ __forceinline__ void seg_sum(float2& s, int b, int e,
                                        const float* __restrict__ T, int lane) {
    int cnt = e - b;
    for (int base = 0; base < cnt; base += 32) {
        int rem = cnt - base;
        int m = rem < 32 ? rem : 32;
        int idx = (lane < m) ? __ldg(&g_csr[b + base + lane]) : 0;
        int k = 0;
        for (; k + 1 < m; k += 2) {
            int c0 = __shfl_sync(0xffffffffu, idx, k);
            int c1 = __shfl_sync(0xffffffffu, idx, k + 1);
            float2 p = *reinterpret_cast<const float2*>(T + (size_t)c0 * 64 + lane * 2);
            float2 q = *reinterpret_cast<const float2*>(T + (size_t)c1 * 64 + lane * 2);
            s.x += p.x + q.x; s.y += p.y + q.y;
        }
        if (k < m) {
            int c0 = __shfl_sync(0xffffffffu, idx, k);
            float2 p = *reinterpret_cast<const float2*>(T + (size_t)c0 * 64 + lane * 2);
            s.x += p.x; s.y += p.y;
        }
    }
}

__global__ void __launch_bounds__(256) k_gather(float* __restrict__ out) {
    // side duty: reset scratch for the next replay (disjoint from gather reads)
    int zidx = blockIdx.x * blockDim.x + threadIdx.x;
    if (zidx < NTOT / 4) reinterpret_cast<int4*>(g_deg)[zidx] = make_int4(0, 0, 0, 0);
    if (zidx < SCAN_NBLK) g_state[zidx] = 0;
    if (zidx < 2) g_novf[zidx] = 0;

    int row = blockIdx.x * 8 + (threadIdx.x >> 5);
    if (row >= NA + NB) return;
    int lane = threadIdx.x & 31;
    float2 s;
    if (row < NA) {
        int cself = __ldg(&g_cidA[row]);
        s = *reinterpret_cast<const float2*>(g_TzA + (size_t)cself * 64 + lane * 2);
        seg_sum(s, g_off[row],      g_off[row + 1],      g_Taa, lane);
        seg_sum(s, g_off[NA + row], g_off[NA + row + 1], g_Tba, lane);
    } else {
        int rb = row - NA;
        int cself = __ldg(&g_cidB[rb]);
        s = *reinterpret_cast<const float2*>(g_TzB + (size_t)cself * 64 + lane * 2);
        seg_sum(s, g_off[2 * NA + rb], g_off[2 * NA + rb + 1], g_Tab, lane);
    }
    s.x = fmaxf(s.x, 0.f); s.y = fmaxf(s.y, 0.f);
    *reinterpret_cast<float2*>(out + (size_t)row * 64 + lane * 2) = s;
}

// ==============================================================================
struct Aux {
    cudaStream_t s2;
    cudaEvent_t evF, evS, evJ;
    Aux() {
        cudaStreamCreateWithFlags(&s2, cudaStreamNonBlocking);
        cudaEventCreateWithFlags(&evF, cudaEventDisableTiming);
        cudaEventCreateWithFlags(&evS, cudaEventDisableTiming);
        cudaEventCreateWithFlags(&evJ, cudaEventDisableTiming);
    }
};

extern "C" void kernel_launch(void* const* d_in, const int* in_sizes, int n_in,
                              void* d_out, int out_size) {
    static Aux aux;

    const int*   src_aa = (const int*)d_in[0];
    const int*   dst_aa = (const int*)d_in[1];
    const int*   src_ab = (const int*)d_in[2];
    const int*   dst_ab = (const int*)d_in[3];
    const int*   src_ba = (const int*)d_in[4];
    const int*   dst_ba = (const int*)d_in[5];
    const float* embA   = (const float*)d_in[6];
    const float* embB   = (const float*)d_in[7];
    const float* Waa    = (const float*)d_in[8];
    const float* baa    = (const float*)d_in[9];
    const float* Wab    = (const float*)d_in[10];
    const float* bab    = (const float*)d_in[11];
    const float* Wba    = (const float*)d_in[12];
    const float* bba    = (const float*)d_in[13];
    const float* WnA    = (const float*)d_in[14];
    const float* bnA    = (const float*)d_in[15];
    const float* WnB    = (const float*)d_in[16];
    const float* bnB    = (const float*)d_in[17];
    const int Eaa = in_sizes[0];
    const int Eab = in_sizes[2];
    const int Eba = in_sizes[4];
    const int Etot = Eaa + Eba + Eab;
    float* out = (float*)d_out;

    // fork: combo-grid tables (weights-only deps) -> s2, overlaps deg+scan
    cudaEventRecord(aux.evF, 0);
    cudaStreamWaitEvent(aux.s2, aux.evF, 0);
    k_tables<<<dim3(CGRID / 128, 5), 256, 0, aux.s2>>>(
        embA, embB, Waa, baa, Wab, bab, Wba, bba, WnA, bnA, WnB, bnB, 0);

    // main chain: deg -> single-pass scan+cid
    k_deg_all<<<(Etot + 255) / 256, 256>>>(dst_aa, Eaa, dst_ba, Eba, dst_ab, Eab);
    k_scan_cid<<<SCAN_NBLK, 1024>>>();

    // overflow rows on s2 (depend on scan); tiny grid, exits when novf==0
    cudaEventRecord(aux.evS, 0);
    cudaStreamWaitEvent(aux.s2, aux.evS, 0);
    k_tables<<<dim3(8, 5), 256, 0, aux.s2>>>(
        embA, embB, Waa, baa, Wab, bab, Wba, bba, WnA, bnA, WnB, bnB, 1);
    cudaEventRecord(aux.evJ, aux.s2);

    k_fill_all<<<(Etot + 255) / 256, 256>>>(src_aa, dst_aa, Eaa,
                                            src_ba, dst_ba, Eba,
                                            src_ab, dst_ab, Eab);

    // join tables; gather (also resets scratch) -> output
    cudaStreamWaitEvent(0, aux.evJ, 0);
    k_gather<<<(NA + NB + 7) / 8, 256>>>(out);
}